// round 5
// baseline (speedup 1.0000x reference)
#include <cuda_runtime.h>
#include <cuda_bf16.h>
#include <math.h>
#include <stdint.h>

#define T_IN  2048
#define F_DIM 256
#define H_DIM 384
#define TP    2051
#define MPAD  2176            // 17 * 128
#define NTOT  1536            // 4 projections * 384
#define TB    384             // b-stride of (t,b) activations
#define NCH   129             // scan chunks
#define CH    16              // t per scan chunk
#define FCH   128             // t per final-dot chunk (17 chunks)
#define INV_SQRT_H 0.05103103703f

// ---------------- scratch (zero-initialized device globals) ------------------
__device__ __align__(16) float g_xp[TP * F_DIM];
__device__ __align__(16) __nv_bfloat16 g_ah[MPAD * F_DIM];  // xp hi (pad rows stay 0)
__device__ __align__(16) __nv_bfloat16 g_al[MPAD * F_DIM];  // xp lo
__device__ __align__(16) __nv_bfloat16 g_bh[NTOT * F_DIM];  // W  hi (k,v,i,f)
__device__ __align__(16) __nv_bfloat16 g_bl[NTOT * F_DIM];  // W  lo
__device__ __align__(16) float g_kb [TP * TB];   // (t,b)
__device__ __align__(16) float g_vb [TP * TB];
__device__ __align__(16) float g_zib[TP * TB];
__device__ __align__(16) float g_lfb[TP * TB];
__device__ __align__(16) float g_cs[NCH * TB];   // chunk sums -> chunk suffixes
__device__ __align__(16) float g_w [NCH * CH];   // w_t (padded with zeros)
__device__ __align__(16) float g_part[17 * TB];  // final dot partials
__device__ float g_qT[H_DIM];
__device__ float g_oT[H_DIM];

// ---------------- mma.sync / ldmatrix helpers (baseline PTX, sm_80+) --------
__device__ __forceinline__ uint32_t smem_u32(const void* p) {
    uint32_t a;
    asm("{ .reg .u64 t; cvta.to.shared.u64 t, %1; cvt.u32.u64 %0, t; }"
        : "=r"(a) : "l"(p));
    return a;
}
#define LDSM4(r0, r1, r2, r3, addr) \
    asm volatile("ldmatrix.sync.aligned.m8n8.x4.shared.b16 {%0,%1,%2,%3}, [%4];" \
                 : "=r"(r0), "=r"(r1), "=r"(r2), "=r"(r3) : "r"(addr))
#define MMA16816(d, a, b) \
    asm volatile("mma.sync.aligned.m16n8k16.row.col.f32.bf16.bf16.f32 " \
                 "{%0,%1,%2,%3},{%4,%5,%6,%7},{%8,%9},{%0,%1,%2,%3};" \
                 : "+f"((d)[0]), "+f"((d)[1]), "+f"((d)[2]), "+f"((d)[3]) \
                 : "r"((a)[0]), "r"((a)[1]), "r"((a)[2]), "r"((a)[3]), \
                   "r"((b)[0]), "r"((b)[1]))

// ---------------- 1. conv + bf16 hi/lo split ---------------------------------
__global__ void conv_cvt(const float* __restrict__ x,
                         const float* __restrict__ cw,
                         const float* __restrict__ cb) {
    int idx = blockIdx.x * blockDim.x + threadIdx.x;   // TP * 64 quads
    if (idx >= TP * (F_DIM / 4)) return;
    int t = idx >> 6, qf = (idx & 63) * 4;
    float b0 = cb[0];
    float4 acc = make_float4(b0, b0, b0, b0);
#pragma unroll
    for (int j = 0; j < 4; ++j) {
        int s = t + j - 3;
        if (s >= 0 && s < T_IN) {
            float4 xv = *reinterpret_cast<const float4*>(&x[s * F_DIM + qf]);
            float w = cw[j];
            acc.x = fmaf(w, xv.x, acc.x); acc.y = fmaf(w, xv.y, acc.y);
            acc.z = fmaf(w, xv.z, acc.z); acc.w = fmaf(w, xv.w, acc.w);
        }
    }
    *reinterpret_cast<float4*>(&g_xp[t * F_DIM + qf]) = acc;
    float vv[4] = {acc.x, acc.y, acc.z, acc.w};
    __nv_bfloat16 hi[4], lo[4];
#pragma unroll
    for (int e = 0; e < 4; ++e) {
        hi[e] = __float2bfloat16_rn(vv[e]);
        lo[e] = __float2bfloat16_rn(vv[e] - __bfloat162float(hi[e]));
    }
    size_t o = (size_t)t * F_DIM + qf;
    *reinterpret_cast<__nv_bfloat162*>(&g_ah[o])     = __nv_bfloat162(hi[0], hi[1]);
    *reinterpret_cast<__nv_bfloat162*>(&g_ah[o + 2]) = __nv_bfloat162(hi[2], hi[3]);
    *reinterpret_cast<__nv_bfloat162*>(&g_al[o])     = __nv_bfloat162(lo[0], lo[1]);
    *reinterpret_cast<__nv_bfloat162*>(&g_al[o + 2]) = __nv_bfloat162(lo[2], lo[3]);
}

// ---------------- 2. pack W -> bf16 hi/lo ------------------------------------
__global__ void cvtB(const float* __restrict__ Wk, const float* __restrict__ Wv,
                     const float* __restrict__ Wi, const float* __restrict__ Wf) {
    int idx = blockIdx.x * blockDim.x + threadIdx.x;   // NTOT * 64 quads
    if (idx >= NTOT * (F_DIM / 4)) return;
    int n = idx >> 6, qf = (idx & 63) * 4;
    int proj = n / H_DIM, r = n % H_DIM;
    const float* W = (proj == 0) ? Wk : (proj == 1) ? Wv : (proj == 2) ? Wi : Wf;
    float4 w = *reinterpret_cast<const float4*>(&W[r * F_DIM + qf]);
    float vv[4] = {w.x, w.y, w.z, w.w};
    __nv_bfloat16 hi[4], lo[4];
#pragma unroll
    for (int e = 0; e < 4; ++e) {
        hi[e] = __float2bfloat16_rn(vv[e]);
        lo[e] = __float2bfloat16_rn(vv[e] - __bfloat162float(hi[e]));
    }
    size_t o = (size_t)n * F_DIM + qf;
    *reinterpret_cast<__nv_bfloat162*>(&g_bh[o])     = __nv_bfloat162(hi[0], hi[1]);
    *reinterpret_cast<__nv_bfloat162*>(&g_bh[o + 2]) = __nv_bfloat162(hi[2], hi[3]);
    *reinterpret_cast<__nv_bfloat162*>(&g_bl[o])     = __nv_bfloat162(lo[0], lo[1]);
    *reinterpret_cast<__nv_bfloat162*>(&g_bl[o + 2]) = __nv_bfloat162(lo[2], lo[3]);
}

// ---------------- 3. q_T, sigmoid(o_T) ---------------------------------------
__global__ void qo_kernel(const float* __restrict__ Wq, const float* __restrict__ bq,
                          const float* __restrict__ Wo, const float* __restrict__ bo) {
    int warp = threadIdx.x >> 5, lane = threadIdx.x & 31;
    int b = blockIdx.x * 8 + warp;
    if (b >= H_DIM) return;
    const float* W  = blockIdx.y ? Wo : Wq;
    const float* bb = blockIdx.y ? bo : bq;
    const float* xr = &g_xp[(TP - 1) * F_DIM];
    float s = 0.f;
    for (int f = lane; f < F_DIM; f += 32) s = fmaf(W[b * F_DIM + f], xr[f], s);
#pragma unroll
    for (int off = 16; off; off >>= 1) s += __shfl_xor_sync(0xffffffffu, s, off);
    if (lane == 0) {
        float z = s + bb[b];
        if (blockIdx.y) g_oT[b] = 1.f / (1.f + expf(-z));
        else            g_qT[b] = z;
    }
}

// ---------------- 4. split-bf16x3 GEMM via mma.sync (fallback HMMA) ----------
// D[2176 x 1536] = xp @ W^T. CTA tile 128x128, warps 2(m) x 4(n) = 64x32 each.
// K = 256 in 8 chunks of 32, double-buffered SMEM, 80B row stride (conflict-free).
#define RS   80               // smem bytes per 32-bf16 row (64B data + 16B pad)
#define ARR  (128 * RS)       // 10240 bytes per tile array
#define SMEM_GEMM (2 * 4 * ARR)   // 81920

__global__ void __launch_bounds__(256, 1)
mma_gemm(const float* __restrict__ bk, const float* __restrict__ bv,
         const float* __restrict__ bi, const float* __restrict__ bf_) {
    extern __shared__ char sm[];
    const uint32_t sb = smem_u32(sm);
    const int tid = threadIdx.x;
    const int lane = tid & 31, wid = tid >> 5;
    const int wm = wid & 1, wn = wid >> 1;          // 2 x 4 warp grid
    const int t0 = blockIdx.x * 128, n0 = blockIdx.y * 128;

    float acc[4][4][4];
#pragma unroll
    for (int i = 0; i < 4; ++i)
#pragma unroll
        for (int j = 0; j < 4; ++j)
#pragma unroll
            for (int e = 0; e < 4; ++e) acc[i][j][e] = 0.f;

    // ldmatrix per-lane offsets
    const uint32_t aOff = (uint32_t)(wm * 64 + (lane & 15)) * RS + ((lane >> 4) * 16);
    const uint32_t bOff = (uint32_t)(wn * 32 + ((lane >> 4) << 3) + (lane & 7)) * RS
                        + (((lane >> 3) & 1) * 16);

    // global<->smem copy mapping: row = tid>>1, two 16B chunks c = (tid&1)*2 + i
    const int cprow = tid >> 1;
    const int cpc0  = (tid & 1) * 2;
    const uint32_t stA = (uint32_t)cprow * RS + cpc0 * 16;

    uint4 pA[2], pAl[2], pB[2], pBl[2];

    // ---- prologue: load chunk 0 into buffer 0 ----
#pragma unroll
    for (int i = 0; i < 2; ++i) {
        int koff = (cpc0 + i) * 8;
        pA [i] = *reinterpret_cast<const uint4*>(&g_ah[(size_t)(t0 + cprow) * F_DIM + koff]);
        pAl[i] = *reinterpret_cast<const uint4*>(&g_al[(size_t)(t0 + cprow) * F_DIM + koff]);
        pB [i] = *reinterpret_cast<const uint4*>(&g_bh[(size_t)(n0 + cprow) * F_DIM + koff]);
        pBl[i] = *reinterpret_cast<const uint4*>(&g_bl[(size_t)(n0 + cprow) * F_DIM + koff]);
    }
#pragma unroll
    for (int i = 0; i < 2; ++i) {
        uint32_t a = stA + i * 16;
        *reinterpret_cast<uint4*>(sm + 0 * ARR + a) = pA[i];
        *reinterpret_cast<uint4*>(sm + 1 * ARR + a) = pAl[i];
        *reinterpret_cast<uint4*>(sm + 2 * ARR + a) = pB[i];
        *reinterpret_cast<uint4*>(sm + 3 * ARR + a) = pBl[i];
    }
    __syncthreads();

    for (int kc = 0; kc < 8; ++kc) {
        if (kc < 7) {
            int kbase = (kc + 1) * 32;
#pragma unroll
            for (int i = 0; i < 2; ++i) {
                int koff = kbase + (cpc0 + i) * 8;
                pA [i] = *reinterpret_cast<const uint4*>(&g_ah[(size_t)(t0 + cprow) * F_DIM + koff]);
                pAl[i] = *reinterpret_cast<const uint4*>(&g_al[(size_t)(t0 + cprow) * F_DIM + koff]);
                pB [i] = *reinterpret_cast<const uint4*>(&g_bh[(size_t)(n0 + cprow) * F_DIM + koff]);
                pBl[i] = *reinterpret_cast<const uint4*>(&g_bl[(size_t)(n0 + cprow) * F_DIM + koff]);
            }
        }
        const uint32_t base = sb + (uint32_t)(kc & 1) * (4 * ARR);
#pragma unroll
        for (int ks = 0; ks < 2; ++ks) {
            uint32_t ah[4][4], al[4][4], bh[4][2], bl[4][2];
            uint32_t aAddr = base + aOff + ks * 32;
#pragma unroll
            for (int mt = 0; mt < 4; ++mt)
                LDSM4(ah[mt][0], ah[mt][1], ah[mt][2], ah[mt][3], aAddr + mt * 16 * RS);
#pragma unroll
            for (int mt = 0; mt < 4; ++mt)
                LDSM4(al[mt][0], al[mt][1], al[mt][2], al[mt][3], aAddr + ARR + mt * 16 * RS);
            uint32_t bAddr = base + 2 * ARR + bOff + ks * 32;
            LDSM4(bh[0][0], bh[0][1], bh[1][0], bh[1][1], bAddr);
            LDSM4(bh[2][0], bh[2][1], bh[3][0], bh[3][1], bAddr + 16 * RS);
            LDSM4(bl[0][0], bl[0][1], bl[1][0], bl[1][1], bAddr + ARR);
            LDSM4(bl[2][0], bl[2][1], bl[3][0], bl[3][1], bAddr + ARR + 16 * RS);
#pragma unroll
            for (int mt = 0; mt < 4; ++mt)
#pragma unroll
                for (int nt = 0; nt < 4; ++nt) {
                    MMA16816(acc[mt][nt], ah[mt], bh[nt]);
                    MMA16816(acc[mt][nt], ah[mt], bl[nt]);
                    MMA16816(acc[mt][nt], al[mt], bh[nt]);
                }
        }
        if (kc < 7) {
            char* dst = sm + ((kc + 1) & 1) * (4 * ARR);
#pragma unroll
            for (int i = 0; i < 2; ++i) {
                uint32_t a = stA + i * 16;
                *reinterpret_cast<uint4*>(dst + 0 * ARR + a) = pA[i];
                *reinterpret_cast<uint4*>(dst + 1 * ARR + a) = pAl[i];
                *reinterpret_cast<uint4*>(dst + 2 * ARR + a) = pB[i];
                *reinterpret_cast<uint4*>(dst + 3 * ARR + a) = pBl[i];
            }
        }
        __syncthreads();
    }

    // ---- epilogue: bias + activation, store (t,b) layout ----
    const int proj = n0 / H_DIM;
    const int cb   = n0 % H_DIM;
    const float* bias = (proj == 0) ? bk : (proj == 1) ? bv : (proj == 2) ? bi : bf_;
    float* outp = (proj == 0) ? g_kb : (proj == 1) ? g_vb : (proj == 2) ? g_zib : g_lfb;
    const int g = lane >> 2, tq = lane & 3;
#pragma unroll
    for (int nt = 0; nt < 4; ++nt) {
        int col = cb + wn * 32 + nt * 8 + tq * 2;
        float2 b2 = *reinterpret_cast<const float2*>(&bias[col]);
#pragma unroll
        for (int mt = 0; mt < 4; ++mt) {
#pragma unroll
            for (int half = 0; half < 2; ++half) {
                int trow = t0 + wm * 64 + mt * 16 + g + half * 8;
                if (trow >= TP) continue;
                float e0 = acc[mt][nt][half * 2 + 0] + b2.x;
                float e1 = acc[mt][nt][half * 2 + 1] + b2.y;
                if (proj == 0) { e0 *= INV_SQRT_H; e1 *= INV_SQRT_H; }
                else if (proj == 3) {
                    e0 = fminf(e0, 0.f) - log1pf(__expf(-fabsf(e0)));
                    e1 = fminf(e1, 0.f) - log1pf(__expf(-fabsf(e1)));
                }
                *reinterpret_cast<float2*>(&outp[(size_t)trow * TB + col]) =
                    make_float2(e0, e1);
            }
        }
    }
}

// ---------------- 5a. per-(chunk,b) sums of log f ----------------------------
__global__ void s1_chunksum() {
    int b = threadIdx.x, c = blockIdx.x;
    float s = 0.f;
#pragma unroll
    for (int i = 0; i < CH; ++i) {
        int t = c * CH + i;
        if (t < TP) s += g_lfb[t * TB + b];
    }
    g_cs[c * TB + b] = s;
}

// ---------------- 5b. suffix-scan over chunks (exclusive) --------------------
__global__ void s2_chunkscan() {
    int b = threadIdx.x;
    float run = 0.f;
#pragma unroll 4
    for (int c = NCH - 1; c >= 0; --c) {
        float s = g_cs[c * TB + b];
        g_cs[c * TB + b] = run;        // suffix over strictly-later chunks
        run += s;
    }
}

// ---------------- 5c. contribs + per-t reduce over b -> w --------------------
__global__ void __launch_bounds__(TB)
s3_contrib() {
    const int b = threadIdx.x, c = blockIdx.x;
    const int wid = b >> 5, lid = b & 31;
    __shared__ float Cs[CH][TB + 1];
    float run = g_cs[c * TB + b];
    float qb  = g_qT[b];
#pragma unroll
    for (int i = CH - 1; i >= 0; --i) {
        int t = c * CH + i;
        float cv = 0.f;
        if (t < TP) {
            float zr = g_zib[t * TB + b] + run;
            if (zr > -80.f) cv = __expf(zr) * g_kb[t * TB + b] * qb;
            run += g_lfb[t * TB + b];
        }
        Cs[i][b] = cv;
    }
    __syncthreads();
#pragma unroll
    for (int p = 0; p < 2; ++p) {
        int i = p * 12 + wid;
        if (i < CH) {
            float s = 0.f;
#pragma unroll
            for (int j = lid; j < TB; j += 32) s += Cs[i][j];
#pragma unroll
            for (int off = 16; off; off >>= 1) s += __shfl_xor_sync(0xffffffffu, s, off);
            if (lid == 0) {
                int t = c * CH + i;
                if (t < TP) g_w[t] = s;
                else if (t < NCH * CH) g_w[t] = 0.f;
            }
        }
    }
}

// ---------------- 6a. partial dots: part[c][a] = sum_t v[t][a] w[t] ----------
__global__ void f1_partial() {
    int a = threadIdx.x, c = blockIdx.x;
    float s = 0.f;
    int tend = min(c * FCH + FCH, TP);
    for (int t = c * FCH; t < tend; ++t)
        s = fmaf(g_vb[t * TB + a], g_w[t], s);
    g_part[c * TB + a] = s;
}

// ---------------- 6b. combine: h[a] ------------------------------------------
__global__ void __launch_bounds__(TB)
f2_combine(float* __restrict__ out) {
    int a = threadIdx.x;
    __shared__ float sd[TB];
    float den = 0.f;
    for (int t = a; t < TP; t += TB) den += g_w[t];
    sd[a] = den;
    __syncthreads();
    if (a < 128) sd[a] += sd[a + 128] + sd[a + 256];
    __syncthreads();
#pragma unroll
    for (int s = 64; s; s >>= 1) {
        if (a < s) sd[a] += sd[a + s];
        __syncthreads();
    }
    float dtot = fmaxf(fabsf(sd[0]), 1.0f);
    float num = 0.f;
#pragma unroll
    for (int c = 0; c < 17; ++c) num += g_part[c * TB + a];
    out[a] = g_oT[a] * num / dtot;
}

// -----------------------------------------------------------------------------
extern "C" void kernel_launch(void* const* d_in, const int* in_sizes, int n_in,
                              void* d_out, int out_size) {
    const float* x  = (const float*)d_in[0];
    const float* Wq = (const float*)d_in[1];  const float* bq = (const float*)d_in[2];
    const float* Wk = (const float*)d_in[3];  const float* bk = (const float*)d_in[4];
    const float* Wv = (const float*)d_in[5];  const float* bv = (const float*)d_in[6];
    const float* Wi = (const float*)d_in[7];  const float* bi = (const float*)d_in[8];
    const float* Wf = (const float*)d_in[9];  const float* bf = (const float*)d_in[10];
    const float* Wo = (const float*)d_in[11]; const float* bo = (const float*)d_in[12];
    const float* cw = (const float*)d_in[13]; const float* cb = (const float*)d_in[14];
    float* out = (float*)d_out;

    static int smem_set = 0;
    if (!smem_set) {
        cudaFuncSetAttribute(mma_gemm, cudaFuncAttributeMaxDynamicSharedMemorySize,
                             SMEM_GEMM);
        smem_set = 1;
    }

    conv_cvt<<<(TP * (F_DIM / 4) + 255) / 256, 256>>>(x, cw, cb);
    cvtB<<<(NTOT * (F_DIM / 4) + 255) / 256, 256>>>(Wk, Wv, Wi, Wf);
    qo_kernel<<<dim3(48, 2), 256>>>(Wq, bq, Wo, bo);
    mma_gemm<<<dim3(MPAD / 128, NTOT / 128), 256, SMEM_GEMM>>>(bk, bv, bi, bf);
    s1_chunksum<<<NCH, TB>>>();
    s2_chunkscan<<<1, TB>>>();
    s3_contrib<<<NCH, TB>>>();
    f1_partial<<<17, TB>>>();
    f2_combine<<<1, TB>>>(out);
}

// round 6
// speedup vs baseline: 1.6347x; 1.6347x over previous
#include <cuda_runtime.h>
#include <cuda_bf16.h>
#include <math.h>
#include <stdint.h>

#define T_IN  2048
#define F_DIM 256
#define H_DIM 384
#define TP    2051
#define MPAD  2176            // 17 * 128
#define NTOT  1536            // 4 projections * 384
#define TB    384             // b-stride of (t,b) activations
#define NCH   129             // scan chunks
#define CH    16              // t per scan chunk
#define INV_SQRT_H 0.05103103703f

// ---------------- scratch (zero-initialized device globals) ------------------
__device__ __align__(16) __nv_bfloat16 g_ah[MPAD * F_DIM];  // xp hi (pad rows 0)
__device__ __align__(16) __nv_bfloat16 g_al[MPAD * F_DIM];  // xp lo
__device__ __align__(16) __nv_bfloat16 g_bh[NTOT * F_DIM];  // W  hi (k,v,i,f)
__device__ __align__(16) __nv_bfloat16 g_bl[NTOT * F_DIM];  // W  lo
__device__ __align__(16) float g_kb [TP * TB];   // (t,b)
__device__ __align__(16) float g_vb [TP * TB];
__device__ __align__(16) float g_zib[TP * TB];
__device__ __align__(16) float g_lfb[TP * TB];
__device__ __align__(16) float g_cs[NCH * TB];   // raw chunk sums of log f
__device__ __align__(16) float g_part[NCH * TB]; // per-chunk partial dots
__device__ float g_wsum[NCH];
__device__ float g_qT[H_DIM];
__device__ float g_oT[H_DIM];

// ---------------- PTX helpers (baseline sm_80+, compile for sm_103) ---------
__device__ __forceinline__ uint32_t smem_u32(const void* p) {
    uint32_t a;
    asm("{ .reg .u64 t; cvta.to.shared.u64 t, %1; cvt.u32.u64 %0, t; }"
        : "=r"(a) : "l"(p));
    return a;
}
#define LDSM4(r0, r1, r2, r3, addr) \
    asm volatile("ldmatrix.sync.aligned.m8n8.x4.shared.b16 {%0,%1,%2,%3}, [%4];" \
                 : "=r"(r0), "=r"(r1), "=r"(r2), "=r"(r3) : "r"(addr))
#define MMA16816(d, a, b) \
    asm volatile("mma.sync.aligned.m16n8k16.row.col.f32.bf16.bf16.f32 " \
                 "{%0,%1,%2,%3},{%4,%5,%6,%7},{%8,%9},{%0,%1,%2,%3};" \
                 : "+f"((d)[0]), "+f"((d)[1]), "+f"((d)[2]), "+f"((d)[3]) \
                 : "r"((a)[0]), "r"((a)[1]), "r"((a)[2]), "r"((a)[3]), \
                   "r"((b)[0]), "r"((b)[1]))
#define CP_ASYNC16(dst, src) \
    asm volatile("cp.async.cg.shared.global [%0], [%1], 16;" \
                 :: "r"(dst), "l"(src) : "memory")
#define CP_COMMIT() asm volatile("cp.async.commit_group;" ::: "memory")
#define CP_WAIT(n)  asm volatile("cp.async.wait_group %0;" :: "n"(n) : "memory")

// ---------------- 1. fused prep: conv+split | W split | q/o GEMV -------------
#define NB_CONV 513           // ceil(TP*64 / 256)
#define NB_CVTB 384           // NTOT*64 / 256
#define NB_QO   96

__global__ void prep(const float* __restrict__ x,
                     const float* __restrict__ cw, const float* __restrict__ cb,
                     const float* __restrict__ Wq, const float* __restrict__ bq,
                     const float* __restrict__ Wo, const float* __restrict__ bo,
                     const float* __restrict__ Wk, const float* __restrict__ Wv,
                     const float* __restrict__ Wi, const float* __restrict__ Wf) {
    const int blk = blockIdx.x;
    if (blk < NB_CONV) {
        int idx = blk * 256 + threadIdx.x;
        if (idx >= TP * (F_DIM / 4)) return;
        int t = idx >> 6, qf = (idx & 63) * 4;
        float b0 = cb[0];
        float4 acc = make_float4(b0, b0, b0, b0);
#pragma unroll
        for (int j = 0; j < 4; ++j) {
            int s = t + j - 3;
            if (s >= 0 && s < T_IN) {
                float4 xv = *reinterpret_cast<const float4*>(&x[s * F_DIM + qf]);
                float w = cw[j];
                acc.x = fmaf(w, xv.x, acc.x); acc.y = fmaf(w, xv.y, acc.y);
                acc.z = fmaf(w, xv.z, acc.z); acc.w = fmaf(w, xv.w, acc.w);
            }
        }
        float vv[4] = {acc.x, acc.y, acc.z, acc.w};
        __nv_bfloat16 hi[4], lo[4];
#pragma unroll
        for (int e = 0; e < 4; ++e) {
            hi[e] = __float2bfloat16_rn(vv[e]);
            lo[e] = __float2bfloat16_rn(vv[e] - __bfloat162float(hi[e]));
        }
        size_t o = (size_t)t * F_DIM + qf;
        *reinterpret_cast<__nv_bfloat162*>(&g_ah[o])     = __nv_bfloat162(hi[0], hi[1]);
        *reinterpret_cast<__nv_bfloat162*>(&g_ah[o + 2]) = __nv_bfloat162(hi[2], hi[3]);
        *reinterpret_cast<__nv_bfloat162*>(&g_al[o])     = __nv_bfloat162(lo[0], lo[1]);
        *reinterpret_cast<__nv_bfloat162*>(&g_al[o + 2]) = __nv_bfloat162(lo[2], lo[3]);
    } else if (blk < NB_CONV + NB_CVTB) {
        int idx = (blk - NB_CONV) * 256 + threadIdx.x;
        int n = idx >> 6, qf = (idx & 63) * 4;
        int proj = n / H_DIM, r = n % H_DIM;
        const float* W = (proj == 0) ? Wk : (proj == 1) ? Wv : (proj == 2) ? Wi : Wf;
        float4 w = *reinterpret_cast<const float4*>(&W[r * F_DIM + qf]);
        float vv[4] = {w.x, w.y, w.z, w.w};
        __nv_bfloat16 hi[4], lo[4];
#pragma unroll
        for (int e = 0; e < 4; ++e) {
            hi[e] = __float2bfloat16_rn(vv[e]);
            lo[e] = __float2bfloat16_rn(vv[e] - __bfloat162float(hi[e]));
        }
        size_t o = (size_t)n * F_DIM + qf;
        *reinterpret_cast<__nv_bfloat162*>(&g_bh[o])     = __nv_bfloat162(hi[0], hi[1]);
        *reinterpret_cast<__nv_bfloat162*>(&g_bh[o + 2]) = __nv_bfloat162(hi[2], hi[3]);
        *reinterpret_cast<__nv_bfloat162*>(&g_bl[o])     = __nv_bfloat162(lo[0], lo[1]);
        *reinterpret_cast<__nv_bfloat162*>(&g_bl[o + 2]) = __nv_bfloat162(lo[2], lo[3]);
    } else {
        // q_T / o_T GEMV. xp_last[f] = cb0 + cw0 * x[2047*F + f] (only j=0 valid).
        int j = blk - NB_CONV - NB_CVTB;          // 0..95
        int type = j & 1, bx = j >> 1;
        int warp = threadIdx.x >> 5, lane = threadIdx.x & 31;
        int b = bx * 8 + warp;
        const float* W  = type ? Wo : Wq;
        const float* bb = type ? bo : bq;
        float cw0 = cw[0], cb0 = cb[0];
        const float* xr = &x[(size_t)2047 * F_DIM];
        float s = 0.f;
        for (int f = lane; f < F_DIM; f += 32)
            s = fmaf(W[b * F_DIM + f], fmaf(cw0, xr[f], cb0), s);
#pragma unroll
        for (int off = 16; off; off >>= 1) s += __shfl_xor_sync(0xffffffffu, s, off);
        if (lane == 0) {
            float z = s + bb[b];
            if (type) g_oT[b] = 1.f / (1.f + expf(-z));
            else      g_qT[b] = z;
        }
    }
}

// ---------------- 2. split-bf16x3 GEMM via mma.sync --------------------------
// D[2176 x 1536] = xp @ W^T. CTA tile 128x192, 384 thr (12 warps 2m x 6n).
// K = 256 in 8 chunks of 32; cp.async double buffer; 80B smem row stride.
#define RS      80
#define AH_OFF  0
#define AL_OFF  10240
#define BH_OFF  20480
#define BL_OFF  35840
#define BUF     51200
#define SMEM_GEMM (2 * BUF)   // 102400

__global__ void __launch_bounds__(384, 1)
mma_gemm(const float* __restrict__ bk, const float* __restrict__ bv,
         const float* __restrict__ bi, const float* __restrict__ bf_) {
    extern __shared__ char sm[];
    const uint32_t sb = smem_u32(sm);
    const int tid = threadIdx.x;
    const int lane = tid & 31, wid = tid >> 5;
    const int wm = wid & 1, wn = wid >> 1;          // 2 x 6 warp grid
    const int t0 = blockIdx.x * 128, n0g = blockIdx.y * 192;

    float acc[4][4][4];
#pragma unroll
    for (int i = 0; i < 4; ++i)
#pragma unroll
        for (int jj = 0; jj < 4; ++jj)
#pragma unroll
            for (int e = 0; e < 4; ++e) acc[i][jj][e] = 0.f;

    const uint32_t aOff = (uint32_t)(wm * 64 + (lane & 15)) * RS + ((lane >> 4) * 16);
    const uint32_t bOff = (uint32_t)(wn * 32 + ((lane >> 4) << 3) + (lane & 7)) * RS
                        + (((lane >> 3) & 1) * 16);

    auto issue_chunk = [&](int kc, int buf) {
        uint32_t dst = sb + (uint32_t)buf * BUF;
        // A: 128 rows x 4 chunks of 16B, hi+lo
        for (int u = tid; u < 512; u += 384) {
            int row = u >> 2, c = u & 3;
            uint32_t a = (uint32_t)row * RS + c * 16;
            size_t g = (size_t)(t0 + row) * F_DIM + kc * 32 + c * 8;
            CP_ASYNC16(dst + AH_OFF + a, &g_ah[g]);
            CP_ASYNC16(dst + AL_OFF + a, &g_al[g]);
        }
        // B: 192 rows x 4 chunks, hi+lo
        for (int u = tid; u < 768; u += 384) {
            int row = u >> 2, c = u & 3;
            uint32_t a = (uint32_t)row * RS + c * 16;
            size_t g = (size_t)(n0g + row) * F_DIM + kc * 32 + c * 8;
            CP_ASYNC16(dst + BH_OFF + a, &g_bh[g]);
            CP_ASYNC16(dst + BL_OFF + a, &g_bl[g]);
        }
        CP_COMMIT();
    };

    issue_chunk(0, 0);
    for (int kc = 0; kc < 8; ++kc) {
        if (kc < 7) { issue_chunk(kc + 1, (kc + 1) & 1); CP_WAIT(1); }
        else        { CP_WAIT(0); }
        __syncthreads();
        const uint32_t base = sb + (uint32_t)(kc & 1) * BUF;
#pragma unroll
        for (int ks = 0; ks < 2; ++ks) {
            uint32_t ah[4][4], al[4][4], bh[4][2], bl[4][2];
            uint32_t aH = base + AH_OFF + aOff + ks * 32;
            uint32_t aL = base + AL_OFF + aOff + ks * 32;
#pragma unroll
            for (int mt = 0; mt < 4; ++mt)
                LDSM4(ah[mt][0], ah[mt][1], ah[mt][2], ah[mt][3], aH + mt * 16 * RS);
#pragma unroll
            for (int mt = 0; mt < 4; ++mt)
                LDSM4(al[mt][0], al[mt][1], al[mt][2], al[mt][3], aL + mt * 16 * RS);
            uint32_t bH = base + BH_OFF + bOff + ks * 32;
            uint32_t bL = base + BL_OFF + bOff + ks * 32;
            LDSM4(bh[0][0], bh[0][1], bh[1][0], bh[1][1], bH);
            LDSM4(bh[2][0], bh[2][1], bh[3][0], bh[3][1], bH + 16 * RS);
            LDSM4(bl[0][0], bl[0][1], bl[1][0], bl[1][1], bL);
            LDSM4(bl[2][0], bl[2][1], bl[3][0], bl[3][1], bL + 16 * RS);
#pragma unroll
            for (int mt = 0; mt < 4; ++mt)
#pragma unroll
                for (int nt = 0; nt < 4; ++nt) {
                    MMA16816(acc[mt][nt], ah[mt], bh[nt]);
                    MMA16816(acc[mt][nt], ah[mt], bl[nt]);
                    MMA16816(acc[mt][nt], al[mt], bh[nt]);
                }
        }
        __syncthreads();
    }

    // ---- epilogue: bias + activation, store (t,b) layout ----
    const int proj = n0g / H_DIM;
    const int cbase = n0g % H_DIM;                 // 0 or 192
    const float* bias = (proj == 0) ? bk : (proj == 1) ? bv : (proj == 2) ? bi : bf_;
    float* outp = (proj == 0) ? g_kb : (proj == 1) ? g_vb : (proj == 2) ? g_zib : g_lfb;
    const int g = lane >> 2, tq = lane & 3;
#pragma unroll
    for (int nt = 0; nt < 4; ++nt) {
        int col = cbase + wn * 32 + nt * 8 + tq * 2;
        float2 b2 = *reinterpret_cast<const float2*>(&bias[col]);
#pragma unroll
        for (int mt = 0; mt < 4; ++mt) {
#pragma unroll
            for (int half = 0; half < 2; ++half) {
                int trow = t0 + wm * 64 + mt * 16 + g + half * 8;
                if (trow >= TP) continue;
                float e0 = acc[mt][nt][half * 2 + 0] + b2.x;
                float e1 = acc[mt][nt][half * 2 + 1] + b2.y;
                if (proj == 0) { e0 *= INV_SQRT_H; e1 *= INV_SQRT_H; }
                else if (proj == 3) {
                    e0 = fminf(e0, 0.f) - log1pf(__expf(-fabsf(e0)));
                    e1 = fminf(e1, 0.f) - log1pf(__expf(-fabsf(e1)));
                }
                *reinterpret_cast<float2*>(&outp[(size_t)trow * TB + col]) =
                    make_float2(e0, e1);
            }
        }
    }
}

// ---------------- 3. per-(chunk,b) sums of log f ------------------------------
__global__ void s1_chunksum() {
    int b = threadIdx.x, c = blockIdx.x;
    float s = 0.f;
#pragma unroll
    for (int i = 0; i < CH; ++i) {
        int t = c * CH + i;
        if (t < TP) s += g_lfb[t * TB + b];
    }
    g_cs[c * TB + b] = s;
}

// ---------------- 4. suffix + contribs + w + partial dots ---------------------
__global__ void __launch_bounds__(TB)
s3_contrib() {
    const int b = threadIdx.x, c = blockIdx.x;
    const int wid = b >> 5, lid = b & 31;
    __shared__ float Cs[CH][TB + 1];
    __shared__ float ws[CH];
    // suffix of chunk sums over chunks strictly later than c
    float run = 0.f;
    for (int cc = c + 1; cc < NCH; ++cc) run += g_cs[cc * TB + b];
    float qb = g_qT[b];
#pragma unroll
    for (int i = CH - 1; i >= 0; --i) {
        int t = c * CH + i;
        float cv = 0.f;
        if (t < TP) {
            float zr = g_zib[t * TB + b] + run;
            if (zr > -80.f) cv = __expf(zr) * g_kb[t * TB + b] * qb;
            run += g_lfb[t * TB + b];
        }
        Cs[i][b] = cv;
    }
    __syncthreads();
#pragma unroll
    for (int p = 0; p < 2; ++p) {
        int i = p * 12 + wid;
        if (i < CH) {
            float s = 0.f;
#pragma unroll
            for (int jj = lid; jj < TB; jj += 32) s += Cs[i][jj];
#pragma unroll
            for (int off = 16; off; off >>= 1) s += __shfl_xor_sync(0xffffffffu, s, off);
            if (lid == 0) ws[i] = s;
        }
    }
    __syncthreads();
    // partial dot over this chunk: pnum[b] = sum_i v[t_i][b] * w[t_i]
    float pnum = 0.f;
#pragma unroll
    for (int i = 0; i < CH; ++i) {
        int t = c * CH + i;
        if (t < TP) pnum = fmaf(g_vb[t * TB + b], ws[i], pnum);
    }
    g_part[c * TB + b] = pnum;
    if (b == 0) {
        float s = 0.f;
#pragma unroll
        for (int i = 0; i < CH; ++i) s += ws[i];
        g_wsum[c] = s;
    }
}

// ---------------- 5. combine: h[a] --------------------------------------------
__global__ void __launch_bounds__(TB)
f2_combine(float* __restrict__ out) {
    int a = threadIdx.x;
    float num = 0.f, den = 0.f;
    for (int c = 0; c < NCH; ++c) num += g_part[c * TB + a];
    for (int c = 0; c < NCH; ++c) den += g_wsum[c];   // broadcast, L1-hit
    out[a] = g_oT[a] * num / fmaxf(fabsf(den), 1.0f);
}

// -----------------------------------------------------------------------------
extern "C" void kernel_launch(void* const* d_in, const int* in_sizes, int n_in,
                              void* d_out, int out_size) {
    const float* x  = (const float*)d_in[0];
    const float* Wq = (const float*)d_in[1];  const float* bq = (const float*)d_in[2];
    const float* Wk = (const float*)d_in[3];  const float* bk = (const float*)d_in[4];
    const float* Wv = (const float*)d_in[5];  const float* bv = (const float*)d_in[6];
    const float* Wi = (const float*)d_in[7];  const float* bi = (const float*)d_in[8];
    const float* Wf = (const float*)d_in[9];  const float* bf = (const float*)d_in[10];
    const float* Wo = (const float*)d_in[11]; const float* bo = (const float*)d_in[12];
    const float* cw = (const float*)d_in[13]; const float* cb = (const float*)d_in[14];
    float* out = (float*)d_out;

    static int smem_set = 0;
    if (!smem_set) {
        cudaFuncSetAttribute(mma_gemm, cudaFuncAttributeMaxDynamicSharedMemorySize,
                             SMEM_GEMM);
        smem_set = 1;
    }

    prep<<<NB_CONV + NB_CVTB + NB_QO, 256>>>(x, cw, cb, Wq, bq, Wo, bo,
                                             Wk, Wv, Wi, Wf);
    mma_gemm<<<dim3(MPAD / 128, NTOT / 192), 384, SMEM_GEMM>>>(bk, bv, bi, bf);
    s1_chunksum<<<NCH, TB>>>();
    s3_contrib<<<NCH, TB>>>();
    f2_combine<<<1, TB>>>(out);
}